// round 5
// baseline (speedup 1.0000x reference)
#include <cuda_runtime.h>
#include <cuda_fp16.h>
#include <cstdint>

// ============================================================================
// CATSCluster fused kernel — sm_103 baseline-PTX tensor path, 2 CTAs/SM,
// direct-fp32 A fragments + continuous B prefetch.
//
//   X = X_data[:, 1:, :]  (16 x 4096 x 2304 fp32)
//   p1 = X[.., 768:1536] -> relu(relu(p1@W1^T)@W2^T) = Ha2   (128)
//   p2 = X[..,1536:2304] -> same weights             = Hb2
//   q  = X[..,   0: 768] -> relu(relu(q @W3^T)@W4^T) = Hq2
//   out = tanh(relu( (Hq2 * |Ha2-Hb2|) @ W5^T ))
//
// Round-5 vs round-4 (396us) / round-3 (369us):
//  * A fragments built straight from the fp32 cp.async staging buffer
//    (LDS.64 x4 + cvt.f16x2 x4 per k16 tile) — no fp16 A image, no convert
//    pass, ONE barrier per chunk instead of two. Stride 288B => the quad
//    float2 pattern is bank-conflict-free.
//  * B fragments from L2 with continuous prefetch: j0 issued before the
//    chunk barrier; each bv[t] reloaded for j+1 right after its MMA.
//    Same prefetch in the layer-2 GEMM.
//  * cp.async for chunk c+1 issued after the barrier (race-free double
//    buffer) and in flight across the whole chunk compute / slice epilogue.
// ============================================================================

// ---- smem layout (bytes), 64-row block ----
static constexpr int A32_STRIDE = 288;                  // 64 f32 + 32B pad (≡8 words mod 32)
static constexpr int A32_BYTES  = 64 * A32_STRIDE;      // 18432
static constexpr int SM_W5   = 0;                       // 512 B
static constexpr int SM_PART = 512;                     // float[64][2]
static constexpr int SM_A32  = 1024;                    // 2 x 18432
static constexpr int SM_H1   = SM_A32 + 2 * A32_BYTES;  // 64 x 528 = 33792
static constexpr int SM_D    = SM_H1 + 64 * 528;        // 64 x 272 = 17408
static constexpr int SMEM_BYTES = SM_D + 64 * 272;      // 89088  (2 CTAs/SM)

// Fragment-packed fp16 weights (prep kernel fills these every launch).
// L1: [chunk 12][n8-tile 32][k16 4][lane 32][4 halves]
// L2: [n8-tile 16][k16 16][lane 32][4 halves]
__device__ __half g_B1[2][12 * 32 * 4 * 32 * 4];   // W1, W3
__device__ __half g_B2[2][16 * 16 * 32 * 4];       // W2, W4

// ---------------------------------------------------------------- helpers
__device__ __forceinline__ uint32_t smem_u32(const void* p) {
    return (uint32_t)__cvta_generic_to_shared(p);
}
__device__ __forceinline__ void ldm_x4(uint32_t r[4], uint32_t addr) {
    asm volatile("ldmatrix.sync.aligned.m8n8.x4.shared.b16 {%0,%1,%2,%3}, [%4];"
                 : "=r"(r[0]), "=r"(r[1]), "=r"(r[2]), "=r"(r[3]) : "r"(addr));
}
__device__ __forceinline__ void mma16816(float c[4], const uint32_t a[4],
                                         uint32_t b0, uint32_t b1) {
    asm volatile(
        "mma.sync.aligned.m16n8k16.row.col.f32.f16.f16.f32 "
        "{%0,%1,%2,%3}, {%4,%5,%6,%7}, {%8,%9}, {%0,%1,%2,%3};"
        : "+f"(c[0]), "+f"(c[1]), "+f"(c[2]), "+f"(c[3])
        : "r"(a[0]), "r"(a[1]), "r"(a[2]), "r"(a[3]), "r"(b0), "r"(b1));
}
__device__ __forceinline__ void cp_async16(uint32_t saddr, const void* gaddr) {
    asm volatile("cp.async.cg.shared.global [%0], [%1], 16;"
                 :: "r"(saddr), "l"(gaddr) : "memory");
}
__device__ __forceinline__ void cp_commit() {
    asm volatile("cp.async.commit_group;" ::: "memory");
}
__device__ __forceinline__ void cp_wait0() {
    asm volatile("cp.async.wait_group 0;" ::: "memory");
}
__device__ __forceinline__ uint32_t h2u(__half2 h) {
    return *reinterpret_cast<uint32_t*>(&h);
}
// load float2 from smem, convert to packed f16x2
__device__ __forceinline__ uint32_t ldcvt(uint32_t saddr) {
    float x, y;
    asm("ld.shared.v2.f32 {%0,%1}, [%2];" : "=f"(x), "=f"(y) : "r"(saddr));
    return h2u(__floats2half2_rn(x, y));
}

// ------------------------------------------------- weight frag-pack kernel
__global__ void prep_kernel(const float* __restrict__ W1, const float* __restrict__ W2,
                            const float* __restrict__ W3, const float* __restrict__ W4) {
    int e = blockIdx.x * blockDim.x + threadIdx.x;    // 0 .. 196607
    {
        // L1 weights: W[n(256)][k(768)]
        int n = e / 768, k = e % 768;
        int kc = k >> 6;
        int j  = (k >> 4) & 3;
        int kl = k & 15;
        int p  = kl >> 3;
        int pos = kl & 7;
        int lane = (n & 7) * 4 + (pos >> 1);
        int h = pos & 1;
        int idx = ((((kc * 32 + (n >> 3)) * 4 + j) * 32 + lane) << 2) + p * 2 + h;
        g_B1[0][idx] = __float2half_rn(W1[e]);
        g_B1[1][idx] = __float2half_rn(W3[e]);
    }
    if (e < 128 * 256) {
        // L2 weights: W[n(128)][k(256)]
        int n = e / 256, k = e % 256;
        int j  = k >> 4;
        int kl = k & 15;
        int p  = kl >> 3;
        int pos = kl & 7;
        int lane = (n & 7) * 4 + (pos >> 1);
        int h = pos & 1;
        int idx = ((((n >> 3) * 16 + j) * 32 + lane) << 2) + p * 2 + h;
        g_B2[0][idx] = __float2half_rn(W2[e]);
        g_B2[1][idx] = __float2half_rn(W4[e]);
    }
}

// ----------------------------------------------------------------- main kernel
__global__ void __launch_bounds__(256, 2) fused_kernel(
    const float* __restrict__ X, const float* __restrict__ W5, float* __restrict__ out) {
    extern __shared__ __align__(128) char smem[];
    const uint32_t sb = smem_u32(smem);
    const int tid = threadIdx.x;
    const int w   = tid >> 5;
    const int l   = tid & 31;
    const int lq  = l & 3;

    const long long blk = blockIdx.x;                  // 1024 blocks, 64 rows each
    const float* Xbase = X + ((blk >> 6) * 4097LL + (blk & 63) * 64LL + 1LL) * 2304LL;

    // chunk c (0..35): slice s=c/12, k-chunk kc=c%12, A32 buffer c&1.
    auto issue_chunk = [&](int c) {
        int ss = c / 12, kk = c % 12;
        int soff = (ss == 0) ? 768 : (ss == 1) ? 1536 : 0;   // p1, p2, q
        const int row = tid >> 2, seg = tid & 3;             // 4 threads/row, 64B each
        const float* src = Xbase + (long long)row * 2304 + soff + kk * 64 + seg * 16;
        uint32_t dst = sb + SM_A32 + (c & 1) * A32_BYTES + row * A32_STRIDE + seg * 64;
        #pragma unroll
        for (int i = 0; i < 4; i++)
            cp_async16(dst + i * 16, src + i * 4);
        cp_commit();
    };

    issue_chunk(0);
    if (tid < 128) ((float*)(smem + SM_W5))[tid] = W5[tid];

    // L1 warp tile: 32m x 64n (grid 2m x 4n).  L2 warp tile: 16m x 64n (4m x 2n).
    const int wm = w >> 2, wq = w & 3;
    const int wm2 = w >> 1, wn2 = w & 1;

    const float* W5s = (const float*)(smem + SM_W5);
    float* parts = (float*)(smem + SM_PART);

    // A fragment base (within a buffer): row = wm*32 + mf*16 + l/4, col = j*16 + (l%4)*2
    const uint32_t aFragBase = sb + SM_A32 + (wm * 32 + (l >> 2)) * A32_STRIDE + lq * 8;

    int c = 0;
    for (int s = 0; s < 3; s++) {
        const uint2* B1g = (const uint2*)g_B1[s == 2 ? 1 : 0];
        const uint2* B2g = (const uint2*)g_B2[s == 2 ? 1 : 0];

        // ================= layer 1: acc[2 mf][8 t][4] = Xslice @ W^T ============
        float acc[2][8][4];
        #pragma unroll
        for (int a = 0; a < 2; a++)
            #pragma unroll
            for (int b = 0; b < 8; b++)
                #pragma unroll
                for (int q = 0; q < 4; q++) acc[a][b][q] = 0.f;

        // preload B j0 of chunk 0 (overlaps the cp wait + barrier below)
        uint2 bv[8];
        {
            const uint2* bG = B1g + wq * 1024 + l;
            #pragma unroll
            for (int t = 0; t < 8; t++) bv[t] = bG[(t * 4) * 32];
        }

        for (int kc = 0; kc < 12; kc++) {
            cp_wait0();
            __syncthreads();                 // chunk c staged & visible; buf (c+1)&1 free
            if (c + 1 < 36) issue_chunk(c + 1);

            const uint32_t aB = aFragBase + (c & 1) * A32_BYTES;
            const uint2* bG  = B1g + kc * 4096 + wq * 1024 + l;
            const uint2* bGn = bG + 4096;    // next chunk (valid when kc<11)

            #pragma unroll
            for (int j = 0; j < 4; j++) {
                // A fragments straight from fp32 smem (conflict-free, stride 288)
                uint32_t a0[4], a1[4];
                const uint32_t ra = aB + j * 64;           // j*16 cols * 4B
                a0[0] = ldcvt(ra);
                a0[1] = ldcvt(ra + 8 * A32_STRIDE);
                a0[2] = ldcvt(ra + 32);
                a0[3] = ldcvt(ra + 8 * A32_STRIDE + 32);
                a1[0] = ldcvt(ra + 16 * A32_STRIDE);
                a1[1] = ldcvt(ra + 24 * A32_STRIDE);
                a1[2] = ldcvt(ra + 16 * A32_STRIDE + 32);
                a1[3] = ldcvt(ra + 24 * A32_STRIDE + 32);
                #pragma unroll
                for (int t = 0; t < 8; t++) {
                    uint32_t b0 = bv[t].x, b1 = bv[t].y;
                    // reload this slot for the next j-step (or next chunk's j0)
                    if (j < 3)            bv[t] = bG[(t * 4 + j + 1) * 32];
                    else if (kc < 11)     bv[t] = bGn[(t * 4) * 32];
                    mma16816(acc[0][t], a0, b0, b1);
                    mma16816(acc[1][t], a1, b0, b1);
                }
            }
            c++;
        }
        // (next slice's chunk 0 already in flight -> overlaps epilogue below)

        // ================= relu -> fp16 -> H1 smem (pad-528B rows) ==============
        #pragma unroll
        for (int mf = 0; mf < 2; mf++) {
            #pragma unroll
            for (int t = 0; t < 8; t++) {
                const int r0 = wm * 32 + mf * 16 + (l >> 2);
                const int col = wq * 64 + t * 8 + lq * 2;
                float* cc = acc[mf][t];
                *(uint32_t*)(smem + SM_H1 + r0 * 528 + col * 2) =
                    h2u(__floats2half2_rn(fmaxf(cc[0], 0.f), fmaxf(cc[1], 0.f)));
                *(uint32_t*)(smem + SM_H1 + (r0 + 8) * 528 + col * 2) =
                    h2u(__floats2half2_rn(fmaxf(cc[2], 0.f), fmaxf(cc[3], 0.f)));
            }
        }
        // preload L2 B j0 (overlaps the barrier)
        uint2 bv2[8];
        {
            const uint2* bG = B2g + wn2 * 4096 + l;
            #pragma unroll
            for (int t = 0; t < 8; t++) bv2[t] = bG[(t * 16) * 32];
        }
        __syncthreads();

        // ================= layer 2: acc2[8 t][4] = H1 @ W2^T ====================
        float acc2[8][4];
        #pragma unroll
        for (int b = 0; b < 8; b++)
            #pragma unroll
            for (int q = 0; q < 4; q++) acc2[b][q] = 0.f;

        {
            const uint32_t aBase = sb + SM_H1 + (wm2 * 16 + (l & 15)) * 528 + (l >> 4) * 16;
            const uint2* bG = B2g + wn2 * 4096 + l;
            #pragma unroll
            for (int j = 0; j < 16; j++) {
                uint32_t afr[4];
                ldm_x4(afr, aBase + j * 32);
                #pragma unroll
                for (int t = 0; t < 8; t++) {
                    uint32_t b0 = bv2[t].x, b1 = bv2[t].y;
                    if (j < 15) bv2[t] = bG[(t * 16 + j + 1) * 32];
                    mma16816(acc2[t], afr, b0, b1);
                }
            }
        }
        // no barrier needed: D-buffer rows/cols below are warp-private, and H1 is
        // next written only after 12 chunk barriers of the following slice.

        // ================= combine via D buffer (pad-272B rows, warp-private) ===
        if (s == 0) {
            #pragma unroll
            for (int t = 0; t < 8; t++) {
                const int r0 = wm2 * 16 + (l >> 2);
                const int col = wn2 * 64 + t * 8 + lq * 2;
                float* cc = acc2[t];
                *(uint32_t*)(smem + SM_D + r0 * 272 + col * 2) =
                    h2u(__floats2half2_rn(fmaxf(cc[0], 0.f), fmaxf(cc[1], 0.f)));
                *(uint32_t*)(smem + SM_D + (r0 + 8) * 272 + col * 2) =
                    h2u(__floats2half2_rn(fmaxf(cc[2], 0.f), fmaxf(cc[3], 0.f)));
            }
        } else if (s == 1) {
            #pragma unroll
            for (int t = 0; t < 8; t++) {
                const int r0 = wm2 * 16 + (l >> 2);
                const int col = wn2 * 64 + t * 8 + lq * 2;
                float* cc = acc2[t];
                uint32_t* d0 = (uint32_t*)(smem + SM_D + r0 * 272 + col * 2);
                uint32_t* d1 = (uint32_t*)(smem + SM_D + (r0 + 8) * 272 + col * 2);
                float2 fa = __half22float2(*(__half2*)d0);
                float2 fb = __half22float2(*(__half2*)d1);
                *d0 = h2u(__floats2half2_rn(fabsf(fa.x - fmaxf(cc[0], 0.f)),
                                            fabsf(fa.y - fmaxf(cc[1], 0.f))));
                *d1 = h2u(__floats2half2_rn(fabsf(fb.x - fmaxf(cc[2], 0.f)),
                                            fabsf(fb.y - fmaxf(cc[3], 0.f))));
            }
        } else {
            float pd[2] = {0.f, 0.f};
            #pragma unroll
            for (int t = 0; t < 8; t++) {
                const int r0 = wm2 * 16 + (l >> 2);
                const int col = wn2 * 64 + t * 8 + lq * 2;
                float* cc = acc2[t];
                float2 da = __half22float2(*(__half2*)(smem + SM_D + r0 * 272 + col * 2));
                float2 db = __half22float2(*(__half2*)(smem + SM_D + (r0 + 8) * 272 + col * 2));
                float w0 = W5s[col], w1 = W5s[col + 1];
                pd[0] += w0 * fmaxf(cc[0], 0.f) * da.x + w1 * fmaxf(cc[1], 0.f) * da.y;
                pd[1] += w0 * fmaxf(cc[2], 0.f) * db.x + w1 * fmaxf(cc[3], 0.f) * db.y;
            }
            #pragma unroll
            for (int rr = 0; rr < 2; rr++) {
                float v = pd[rr];
                v += __shfl_xor_sync(0xFFFFFFFF, v, 1);
                v += __shfl_xor_sync(0xFFFFFFFF, v, 2);
                if (lq == 0) {
                    int row = wm2 * 16 + rr * 8 + (l >> 2);
                    parts[row * 2 + wn2] = v;
                }
            }
        }
    }

    __syncthreads();
    if (tid < 64) {
        float sum = parts[tid * 2] + parts[tid * 2 + 1];
        out[blk * 64 + tid] = tanhf(fmaxf(sum, 0.f));
    }
}

// ------------------------------------------------------------------- launcher
extern "C" void kernel_launch(void* const* d_in, const int* in_sizes, int n_in,
                              void* d_out, int out_size) {
    const float* X  = (const float*)d_in[0];
    const float* W1 = (const float*)d_in[1];
    const float* W2 = (const float*)d_in[2];
    const float* W3 = (const float*)d_in[3];
    const float* W4 = (const float*)d_in[4];
    const float* W5 = (const float*)d_in[5];
    (void)in_sizes; (void)n_in; (void)out_size;

    cudaFuncSetAttribute(fused_kernel, cudaFuncAttributeMaxDynamicSharedMemorySize, SMEM_BYTES);

    prep_kernel<<<768, 256>>>(W1, W2, W3, W4);
    fused_kernel<<<1024, 256, SMEM_BYTES>>>(X, W5, (float*)d_out);
}